// round 13
// baseline (speedup 1.0000x reference)
#include <cuda_runtime.h>

// Piecewise-linear log-sigmoid approximation (table interp).
// inputs: vals[64*2048*2048] f32, x[65] f32 (uniform linspace), y[65] f32
// output: f32 same shape.
//
// Semantics (matches jax reference):
//   v <  x[0]  -> v
//   v >= x[64] -> 0
//   else out = y[i] + (v - x[i]) * slope[i],  i = floor((v-x0)/h) clamped
//
// 256-bit (v8.f32) global loads/stores (sm_100+), grid-stride with fixed
// trip count, ILP=4 x v8 per thread per iteration, front-batched loads,
// 32-bit indexing.

#define NBP  65
#define NSEG 64
#define ILP  4          // v8 vectors per thread per iteration
#define THREADS 256
#define BLOCKS  4096
// floats per grid-iter: 4096 * 256 * 4 * 8 = 2^25 ; n = 2^28 -> 8 iterations.

struct f8 { float v[8]; };

__device__ __forceinline__ f8 ldg256_cs(const float* p) {
    f8 r;
    asm volatile(
        "ld.global.cs.v8.f32 {%0,%1,%2,%3,%4,%5,%6,%7}, [%8];"
        : "=f"(r.v[0]), "=f"(r.v[1]), "=f"(r.v[2]), "=f"(r.v[3]),
          "=f"(r.v[4]), "=f"(r.v[5]), "=f"(r.v[6]), "=f"(r.v[7])
        : "l"(p));
    return r;
}

__device__ __forceinline__ void stg256_cs(float* p, const f8& x) {
    asm volatile(
        "st.global.cs.v8.f32 [%0], {%1,%2,%3,%4,%5,%6,%7,%8};"
        :: "l"(p),
           "f"(x.v[0]), "f"(x.v[1]), "f"(x.v[2]), "f"(x.v[3]),
           "f"(x.v[4]), "f"(x.v[5]), "f"(x.v[6]), "f"(x.v[7])
        : "memory");
}

__global__ __launch_bounds__(THREADS) void logsig_kernel(
        const float* __restrict__ vals,
        const float* __restrict__ xs,
        const float* __restrict__ ys,
        float* __restrict__ out,
        unsigned int niter)
{
    // Per-segment affine coefficients: r = c.x + c.y * v
    __shared__ float2 coef[NSEG];
    __shared__ float s_x0, s_xlast, s_invh;

    const unsigned int t = threadIdx.x;
    if (t < NSEG) {
        float x0 = xs[t];
        float x1 = xs[t + 1];
        float y0 = ys[t];
        float y1 = ys[t + 1];
        float slope = (y1 - y0) / (x1 - x0);
        coef[t] = make_float2(fmaf(-x0, slope, y0), slope);
    }
    if (t == 0) {
        float a = xs[0];
        float b = xs[NBP - 1];
        s_x0    = a;
        s_xlast = b;
        s_invh  = (float)NSEG / (b - a);
    }
    __syncthreads();

    const float x0    = s_x0;
    const float xlast = s_xlast;
    const float invh  = s_invh;

    // Indices below are in units of v8 (8 floats = 32 bytes).
    const unsigned int stride = (unsigned int)gridDim.x * (THREADS * ILP);
    unsigned int base = blockIdx.x * (THREADS * ILP) + t;

    for (unsigned int it = 0; it < niter; it++, base += stride) {
        f8 v[ILP];
        // Front-batch all 256-bit loads (deep MLP), streaming hint
        #pragma unroll
        for (int j = 0; j < ILP; j++)
            v[j] = ldg256_cs(vals + (unsigned long long)(base + j * THREADS) * 8ull);

        #pragma unroll
        for (int j = 0; j < ILP; j++) {
            f8 o;
            #pragma unroll
            for (int k = 0; k < 8; k++) {
                float val = v[j].v[k];
                int idx = (int)((val - x0) * invh);
                idx = max(0, min(idx, NSEG - 1));
                float2 c = coef[idx];
                float r = fmaf(c.y, val, c.x);
                r = (val <  x0)    ? val  : r;
                r = (val >= xlast) ? 0.0f : r;
                o.v[k] = r;
            }
            stg256_cs(out + (unsigned long long)(base + j * THREADS) * 8ull, o);
        }
    }
}

extern "C" void kernel_launch(void* const* d_in, const int* in_sizes, int n_in,
                              void* d_out, int out_size)
{
    const float* vals = (const float*)d_in[0];
    const float* xs   = (const float*)d_in[1];
    const float* ys   = (const float*)d_in[2];
    float* out        = (float*)d_out;

    unsigned int n8 = (unsigned int)(out_size / 8);          // 2^25 v8 units
    unsigned int per_iter = BLOCKS * THREADS * ILP;          // 2^22 v8 units
    unsigned int niter = (n8 + per_iter - 1) / per_iter;     // 8 for this shape

    logsig_kernel<<<BLOCKS, THREADS>>>(vals, xs, ys, out, niter);
}